// round 15
// baseline (speedup 1.0000x reference)
#include <cuda_runtime.h>
#include <math.h>

// ---------------- problem constants ----------------
#define SLOTS      85      // 81 classes + 4 box coords
#define NBINS      2048
#define HIST_LO   (-8.0f)
#define HIST_INVW (128.0f)   // NBINS / 16
#define NBLOCKS    444       // 3 blocks/SM (pinned) * 148 SMs = ONE wave
#define UNROLL     16        // anchors per warp per iteration (16*340B = 16B-aligned)
#define TILE_F4    340       // float4s per tile = 16*85/4

// ---------------- device scratch (statically zero-initialized; the fused
// finalize tail re-zeroes everything at the end of every replay) -----------
__device__ int      g_npos;
__device__ double   g_pos_loss;
__device__ double   g_loc_loss;
__device__ int      g_hist_cnt[NBINS];
__device__ float    g_hist_sum[NBINS];
__device__ unsigned g_done;

// ---------------- K1: flat float4 stream, warp = 16 anchors ----------------
// y_true class rows are one-hot. The 16-anchor tile (5440 B, always 16B
// aligned) is streamed as 340 float4s: 10 full rounds + a 20-lane partial.
// Demux AFTER load: each nonzero element maps idx -> (anchor j, slot s);
// class slots OR into packed-hot words (one-hot => OR order-independent).
// Box slots (s>80, always nonzero) are excluded; positives (~2%) reload
// their 4 box floats. conf = -y_pred[hot]; bg logit preloaded for negatives.
// The LAST block to finish runs the histogram top-k scan inline.
__global__ __launch_bounds__(256, 3) void ssd_main_kernel(
    const float* __restrict__ yp,
    const float* __restrict__ yt,
    int nanch,
    float* __restrict__ out)
{
    __shared__ int   s_cnt[NBINS];
    __shared__ float s_sum[NBINS];
    __shared__ int   s_wsum[8];
    __shared__ int   s_woff[8];
    __shared__ double s_neg;
    __shared__ int   s_last;

    for (int i = threadIdx.x; i < NBINS; i += 256) { s_cnt[i] = 0; s_sum[i] = 0.0f; }
    __syncthreads();

    const int lane = threadIdx.x & 31;
    const int warp = threadIdx.x >> 5;

    const int wid    = blockIdx.x * 8 + warp;
    const int stride = NBLOCKS * 8 * UNROLL;     // anchors per grid step

    float accPos = 0.0f, accLoc = 0.0f;
    int   accN = 0;

    for (int a0 = wid * UNROLL; a0 < nanch; a0 += stride) {
        const unsigned base = (unsigned)a0 * SLOTS;       // float index

        if (a0 + UNROLL <= nanch) {
            // ---- 11 front-batched LDG.128 per lane (dense aligned stream) ----
            const float4* p4 = (const float4*)yt + (base >> 2);  // base%4==0
            float4 v[11];
            #pragma unroll
            for (int k = 0; k < 10; k++)
                v[k] = p4[k * 32 + lane];
            v[10] = (lane < TILE_F4 - 320)                // lanes 0..19
                  ? p4[320 + lane]
                  : make_float4(0.0f, 0.0f, 0.0f, 0.0f);

            // background logits: lane j<16 loads yp[(a0+j)*SLOTS]
            float bg = (lane < UNROLL) ? yp[base + (unsigned)lane * SLOTS] : 0.0f;

            // ---- demux: nonzero elements -> (anchor, slot); OR-pack hots ----
            unsigned pk[4] = {0u, 0u, 0u, 0u};
            #pragma unroll
            for (int k = 0; k < 11; k++) {
                float4 q = v[k];
                if (q.x != 0.0f || q.y != 0.0f || q.z != 0.0f || q.w != 0.0f) {
                    int i4 = (k * 32 + lane) * 4;
                    #pragma unroll
                    for (int e = 0; e < 4; e++) {
                        float val = (e == 0) ? q.x : (e == 1) ? q.y
                                  : (e == 2) ? q.z : q.w;
                        if (val != 0.0f) {
                            int idx = i4 + e;             // 0..1359
                            int j = idx / 85;             // anchor in tile
                            int s = idx - j * 85;         // slot
                            if (s >= 1 && s <= 80)        // class slot only
                                pk[j >> 2] |= (unsigned)s << ((j & 3) * 8);
                        }
                    }
                }
            }
            pk[0] = __reduce_or_sync(0xffffffffu, pk[0]);
            pk[1] = __reduce_or_sync(0xffffffffu, pk[1]);
            pk[2] = __reduce_or_sync(0xffffffffu, pk[2]);
            pk[3] = __reduce_or_sync(0xffffffffu, pk[3]);

            // ---- per-anchor bookkeeping: lane j (0..15) owns anchor j ----
            if (lane < UNROLL) {
                unsigned pw = pk[lane >> 2];
                int h = (int)((pw >> ((lane & 3) * 8)) & 0xffu);
                if (h > 0) {                          // positive (~2%): gather
                    float conf = -yp[base + (unsigned)lane * SLOTS + h];
                    accN++; accPos += conf;
                } else {                              // negative: bg preloaded
                    float conf = -bg;
                    int bin = (int)((conf - HIST_LO) * HIST_INVW);
                    bin = max(0, min(NBINS - 1, bin));
                    atomicAdd(&s_cnt[bin], 1);
                    atomicAdd(&s_sum[bin], conf);
                }
            }

            // ---- box smooth-L1, pass 1: anchors 0..7 (all 32 lanes) ----
            {
                int j = lane >> 2;                    // 0..7
                unsigned pw = (j < 4) ? pk[0] : pk[1];
                int h = (int)((pw >> ((j & 3) * 8)) & 0xffu);
                if (h > 0) {                          // positives only (~2%)
                    unsigned rb = base + (unsigned)j * SLOTS + 81 + (lane & 3);
                    float d  = yp[rb] - yt[rb];
                    float ad = fabsf(d);
                    accLoc += (ad < 1.0f) ? 0.5f * d * d : (ad - 0.5f);
                }
            }
            // ---- box smooth-L1, pass 2: anchors 8..15 (all 32 lanes) ----
            {
                int j = 8 + (lane >> 2);              // 8..15
                unsigned pw = (j < 12) ? pk[2] : pk[3];
                int h = (int)((pw >> ((j & 3) * 8)) & 0xffu);
                if (h > 0) {
                    unsigned rb = base + (unsigned)j * SLOTS + 81 + (lane & 3);
                    float d  = yp[rb] - yt[rb];
                    float ad = fabsf(d);
                    accLoc += (ad < 1.0f) ? 0.5f * d * d : (ad - 0.5f);
                }
            }
        } else {
            // ---- tail: per-anchor fallback (nanch % 16 may be 0; safe) ----
            for (int j = 0; j < UNROLL; j++) {
                if (a0 + j >= nanch) break;
                unsigned r = base + (unsigned)j * SLOTS;
                float t0 = yt[r + lane];
                float t1 = yt[r + lane + 32];
                float t2 = (lane < 17) ? yt[r + lane + 64] : 0.0f;
                int la = -1;
                if (t0 != 0.0f) la = lane;
                if (t1 != 0.0f) la = lane + 32;
                if (t2 != 0.0f) la = lane + 64;
                int hot = max(__reduce_max_sync(0xffffffffu, la), 0);
                if (lane == 0) {
                    float conf = -yp[r + hot];
                    if (hot > 0) { accN++; accPos += conf; }
                    else {
                        int bin = (int)((conf - HIST_LO) * HIST_INVW);
                        bin = max(0, min(NBINS - 1, bin));
                        atomicAdd(&s_cnt[bin], 1);
                        atomicAdd(&s_sum[bin], conf);
                    }
                }
                if (hot > 0 && lane >= 17 && lane < 21) {
                    unsigned rb = r + lane + 64;
                    float d  = yp[rb] - yt[rb];
                    float ad = fabsf(d);
                    accLoc += (ad < 1.0f) ? 0.5f * d * d : (ad - 0.5f);
                }
            }
        }
    }

    // ---- warp flush: reduce scattered accumulators, one atomic set per warp
    #pragma unroll
    for (int off = 16; off; off >>= 1) {
        accPos += __shfl_down_sync(0xffffffffu, accPos, off);
        accLoc += __shfl_down_sync(0xffffffffu, accLoc, off);
    }
    int warpN = __reduce_add_sync(0xffffffffu, accN);

    if (lane == 0) {
        if (warpN) {
            atomicAdd(&g_npos, warpN);
            atomicAdd(&g_pos_loss, (double)accPos);
        }
        if (accLoc != 0.0f) atomicAdd(&g_loc_loss, (double)accLoc);
    }

    __syncthreads();
    for (int i = threadIdx.x; i < NBINS; i += 256) {
        int cc = s_cnt[i];
        if (cc) {
            atomicAdd(&g_hist_cnt[i], cc);
            atomicAdd(&g_hist_sum[i], s_sum[i]);
        }
    }

    // ================= fused finalize: last block does the top-k scan =======
    __threadfence();                       // make this block's writes visible
    __syncthreads();
    if (threadIdx.x == 0) {
        unsigned old = atomicAdd(&g_done, 1u);
        s_last = (old == (unsigned)(gridDim.x - 1)) ? 1 : 0;
    }
    __syncthreads();
    if (!s_last) return;

    __threadfence();                       // acquire all blocks' writes

    const int tid = threadIdx.x;
    const int wrp = tid >> 5;

    // thread owns 8 consecutive ranks from the top: rank i -> bin NBINS-1-i
    int   c[8];
    float sf[8];
    #pragma unroll
    for (int k = 0; k < 8; k++) {
        int b = NBINS - 1 - (tid * 8 + k);
        c[k]  = g_hist_cnt[b];
        sf[k] = g_hist_sum[b];
    }
    int total = 0;
    #pragma unroll
    for (int k = 0; k < 8; k++) total += c[k];

    // warp-local inclusive scan of per-thread totals
    int scan = total;
    #pragma unroll
    for (int off = 1; off < 32; off <<= 1) {
        int v = __shfl_up_sync(0xffffffffu, scan, off);
        if (lane >= off) scan += v;
    }
    if (lane == 31) s_wsum[wrp] = scan;
    if (tid == 0)   s_neg = 0.0;
    __syncthreads();

    // warp 0 scans the 8 warp totals -> exclusive warp offsets
    if (wrp == 0) {
        int w = (lane < 8) ? s_wsum[lane] : 0;
        int ws = w;
        #pragma unroll
        for (int off = 1; off < 8; off <<= 1) {
            int v = __shfl_up_sync(0xffffffffu, ws, off);
            if (lane >= off) ws += v;
        }
        if (lane < 8) s_woff[lane] = ws - w;   // exclusive prefix
    }
    __syncthreads();

    int cumBefore = s_woff[wrp] + (scan - total);  // negatives strictly above

    int npos = g_npos;
    int nneg = (int)(3.0f * (float)npos);

    double contrib = 0.0;
    int cb = cumBefore;
    #pragma unroll
    for (int k = 0; k < 8; k++) {
        int cc = c[k];
        if (cc) {
            if (cb + cc <= nneg) {
                contrib += (double)sf[k];                                    // fully taken
            } else if (cb < nneg) {
                contrib += (double)sf[k] * (double)(nneg - cb) / (double)cc; // straddling
            }
        }
        cb += cc;
    }

    // warp-reduce contrib, one shared atomic per warp
    #pragma unroll
    for (int off = 16; off; off >>= 1)
        contrib += __shfl_down_sync(0xffffffffu, contrib, off);
    if (lane == 0 && contrib != 0.0) atomicAdd(&s_neg, contrib);
    __syncthreads();

    if (tid == 0) {
        double np = (npos > 0) ? (double)npos : 1.0;
        out[0] = (float)((g_pos_loss + s_neg + g_loc_loss) / np);
    }

    // ---- re-zero scratch so the next graph replay starts clean ----
    __syncthreads();
    for (int i = tid; i < NBINS; i += 256) {
        g_hist_cnt[i] = 0;
        g_hist_sum[i] = 0.0f;
    }
    if (tid == 0) {
        g_npos = 0; g_pos_loss = 0.0; g_loc_loss = 0.0; g_done = 0u;
    }
}

// ---------------- entry point ----------------
extern "C" void kernel_launch(void* const* d_in, const int* in_sizes, int n_in,
                              void* d_out, int out_size)
{
    const float* y_pred = (const float*)d_in[0];
    const float* y_true = (const float*)d_in[1];
    float* out = (float*)d_out;

    int nanch = in_sizes[0] / SLOTS;

    ssd_main_kernel<<<NBLOCKS, 256>>>(y_pred, y_true, nanch, out);
}

// round 16
// speedup vs baseline: 1.2454x; 1.2454x over previous
#include <cuda_runtime.h>
#include <math.h>

// ---------------- problem constants ----------------
#define SLOTS      85      // 81 classes + 4 box coords
#define NBINS      1024
#define HIST_LO   (-8.0f)
#define HIST_INVW (64.0f)    // NBINS / 16
#define NBLOCKS    592       // 4 blocks/SM (pinned) * 148 SMs = ONE wave
#define UNROLL     12        // anchors per warp per iteration

// ---------------- device scratch (statically zero-initialized; the fused
// finalize tail re-zeroes everything at the end of every replay) -----------
__device__ int      g_npos;
__device__ double   g_pos_loss;
__device__ double   g_loc_loss;
__device__ int      g_hist_cnt[NBINS];
__device__ float    g_hist_sum[NBINS];
__device__ unsigned g_done;

// ---------------- K1: one-hot gather pass, warp = 12 anchors ---------------
// y_true class rows are one-hot: conf = -y_pred[hot]. 37 independent LDGs are
// front-batched per iteration (12 anchors x 3 yt rows + 12 bg logits via one
// predicated LDG). Hot slots OR-packed (8 bits/anchor, 3 words) and reduced
// with THREE __reduce_or_sync ops. Last block runs the top-k scan inline.
// Body compiles to 64 regs; 64*256*4 = full RF -> 4 resident blocks/SM.
__global__ __launch_bounds__(256, 4) void ssd_main_kernel(
    const float* __restrict__ yp,
    const float* __restrict__ yt,
    int nanch,
    float* __restrict__ out)
{
    __shared__ int   s_cnt[NBINS];
    __shared__ float s_sum[NBINS];
    __shared__ int   s_wsum[8];
    __shared__ int   s_woff[8];
    __shared__ double s_neg;
    __shared__ int   s_last;

    for (int i = threadIdx.x; i < NBINS; i += 256) { s_cnt[i] = 0; s_sum[i] = 0.0f; }
    __syncthreads();

    const int lane = threadIdx.x & 31;
    const int warp = threadIdx.x >> 5;

    const int wid    = blockIdx.x * 8 + warp;
    const int stride = NBLOCKS * 8 * UNROLL;     // anchors per grid step

    float accPos = 0.0f, accLoc = 0.0f;
    int   accN = 0;

    for (int a0 = wid * UNROLL; a0 < nanch; a0 += stride) {
        const unsigned base = (unsigned)a0 * SLOTS;   // fits: nanch*85 < 2^31

        if (a0 + UNROLL <= nanch) {
            // ---- 36 front-batched yt loads (immediates off one base) ----
            float ta[UNROLL], tb[UNROLL], tc[UNROLL];
            #pragma unroll
            for (int j = 0; j < UNROLL; j++) {
                ta[j] = yt[base + j * SLOTS + lane];
                tb[j] = yt[base + j * SLOTS + lane + 32];
                tc[j] = (lane < 17) ? yt[base + j * SLOTS + lane + 64] : 0.0f;
            }
            // background logits: lane j<12 loads yp[(a0+j)*SLOTS]
            float bg = (lane < UNROLL) ? yp[base + lane * SLOTS] : 0.0f;

            // ---- hot slots: OR-pack 4 anchors per word, 3 redux total ----
            // one-hot rows => at most one lane contributes per anchor, and
            // slot 0 (background) ORs as 0, which is exactly hot==0.
            unsigned pk[3] = {0u, 0u, 0u};
            #pragma unroll
            for (int j = 0; j < UNROLL; j++) {
                unsigned slot = 0u;
                if (ta[j] != 0.0f) slot = (unsigned)lane;
                if (tb[j] != 0.0f) slot = (unsigned)(lane + 32);
                if (tc[j] != 0.0f) slot = (unsigned)(lane + 64);  // lane<17 only
                pk[j >> 2] |= slot << ((j & 3) * 8);
            }
            pk[0] = __reduce_or_sync(0xffffffffu, pk[0]);
            pk[1] = __reduce_or_sync(0xffffffffu, pk[1]);
            pk[2] = __reduce_or_sync(0xffffffffu, pk[2]);

            // ---- per-anchor bookkeeping: lane j (0..11) owns anchor j ----
            if (lane < UNROLL) {
                unsigned pw = (lane < 4) ? pk[0] : ((lane < 8) ? pk[1] : pk[2]);
                int h = (int)((pw >> ((lane & 3) * 8)) & 0xffu);
                if (h > 0) {                          // positive (~2%): gather
                    float conf = -yp[base + lane * SLOTS + h];
                    accN++; accPos += conf;
                } else {                              // negative: bg preloaded
                    float conf = -bg;
                    int bin = (int)((conf - HIST_LO) * HIST_INVW);
                    bin = max(0, min(NBINS - 1, bin));
                    atomicAdd(&s_cnt[bin], 1);
                    atomicAdd(&s_sum[bin], conf);
                }
            }

            // ---- box smooth-L1, pass 1: anchors 0..7 (all 32 lanes) ----
            {
                int j = lane >> 2;                    // 0..7
                unsigned pw = (j < 4) ? pk[0] : pk[1];
                int h = (int)((pw >> ((j & 3) * 8)) & 0xffu);
                if (h > 0) {                          // positives only (~2%)
                    unsigned rb = base + j * SLOTS + 81 + (lane & 3);
                    float d  = yp[rb] - yt[rb];
                    float ad = fabsf(d);
                    accLoc += (ad < 1.0f) ? 0.5f * d * d : (ad - 0.5f);
                }
            }
            // ---- box smooth-L1, pass 2: anchors 8..11 (lanes 0..15) ----
            if (lane < 16) {
                int j = 8 + (lane >> 2);              // 8..11
                int h = (int)((pk[2] >> (((lane >> 2) & 3) * 8)) & 0xffu);
                if (h > 0) {
                    unsigned rb = base + j * SLOTS + 81 + (lane & 3);
                    float d  = yp[rb] - yt[rb];
                    float ad = fabsf(d);
                    accLoc += (ad < 1.0f) ? 0.5f * d * d : (ad - 0.5f);
                }
            }
        } else {
            // ---- tail: per-anchor fallback (nanch % 12 == 0 here, but safe)
            for (int j = 0; j < UNROLL; j++) {
                if (a0 + j >= nanch) break;
                unsigned r = base + j * SLOTS;
                float t0 = yt[r + lane];
                float t1 = yt[r + lane + 32];
                float t2 = (lane < 17) ? yt[r + lane + 64] : 0.0f;
                int la = -1;
                if (t0 != 0.0f) la = lane;
                if (t1 != 0.0f) la = lane + 32;
                if (t2 != 0.0f) la = lane + 64;
                int hot = max(__reduce_max_sync(0xffffffffu, la), 0);
                if (lane == 0) {
                    float conf = -yp[r + hot];
                    if (hot > 0) { accN++; accPos += conf; }
                    else {
                        int bin = (int)((conf - HIST_LO) * HIST_INVW);
                        bin = max(0, min(NBINS - 1, bin));
                        atomicAdd(&s_cnt[bin], 1);
                        atomicAdd(&s_sum[bin], conf);
                    }
                }
                if (hot > 0 && lane >= 17 && lane < 21) {
                    unsigned rb = r + lane + 64;
                    float d  = yp[rb] - yt[rb];
                    float ad = fabsf(d);
                    accLoc += (ad < 1.0f) ? 0.5f * d * d : (ad - 0.5f);
                }
            }
        }
    }

    // ---- warp flush: reduce scattered accumulators, one atomic set per warp
    #pragma unroll
    for (int off = 16; off; off >>= 1) {
        accPos += __shfl_down_sync(0xffffffffu, accPos, off);
        accLoc += __shfl_down_sync(0xffffffffu, accLoc, off);
    }
    int warpN = __reduce_add_sync(0xffffffffu, accN);

    if (lane == 0) {
        if (warpN) {
            atomicAdd(&g_npos, warpN);
            atomicAdd(&g_pos_loss, (double)accPos);
        }
        if (accLoc != 0.0f) atomicAdd(&g_loc_loss, (double)accLoc);
    }

    __syncthreads();
    for (int i = threadIdx.x; i < NBINS; i += 256) {
        int cc = s_cnt[i];
        if (cc) {
            atomicAdd(&g_hist_cnt[i], cc);
            atomicAdd(&g_hist_sum[i], s_sum[i]);
        }
    }

    // ================= fused finalize: last block does the top-k scan =======
    __threadfence();                       // make this block's writes visible
    __syncthreads();
    if (threadIdx.x == 0) {
        unsigned old = atomicAdd(&g_done, 1u);
        s_last = (old == (unsigned)(gridDim.x - 1)) ? 1 : 0;
    }
    __syncthreads();
    if (!s_last) return;

    __threadfence();                       // acquire all blocks' writes

    const int tid = threadIdx.x;
    const int wrp = tid >> 5;

    // thread owns 4 consecutive ranks from the top: rank i -> bin NBINS-1-i
    int   c[4];
    float sf[4];
    #pragma unroll
    for (int k = 0; k < 4; k++) {
        int b = NBINS - 1 - (tid * 4 + k);
        c[k]  = g_hist_cnt[b];
        sf[k] = g_hist_sum[b];
    }
    int total = c[0] + c[1] + c[2] + c[3];

    // warp-local inclusive scan of per-thread totals
    int scan = total;
    #pragma unroll
    for (int off = 1; off < 32; off <<= 1) {
        int v = __shfl_up_sync(0xffffffffu, scan, off);
        if (lane >= off) scan += v;
    }
    if (lane == 31) s_wsum[wrp] = scan;
    if (tid == 0)   s_neg = 0.0;
    __syncthreads();

    // warp 0 scans the 8 warp totals -> exclusive warp offsets
    if (wrp == 0) {
        int w = (lane < 8) ? s_wsum[lane] : 0;
        int ws = w;
        #pragma unroll
        for (int off = 1; off < 8; off <<= 1) {
            int v = __shfl_up_sync(0xffffffffu, ws, off);
            if (lane >= off) ws += v;
        }
        if (lane < 8) s_woff[lane] = ws - w;   // exclusive prefix
    }
    __syncthreads();

    int cumBefore = s_woff[wrp] + (scan - total);  // negatives strictly above

    int npos = g_npos;
    int nneg = (int)(3.0f * (float)npos);

    double contrib = 0.0;
    int cb = cumBefore;
    #pragma unroll
    for (int k = 0; k < 4; k++) {
        int cc = c[k];
        if (cc) {
            if (cb + cc <= nneg) {
                contrib += (double)sf[k];                                    // fully taken
            } else if (cb < nneg) {
                contrib += (double)sf[k] * (double)(nneg - cb) / (double)cc; // straddling
            }
        }
        cb += cc;
    }

    // warp-reduce contrib, one shared atomic per warp
    #pragma unroll
    for (int off = 16; off; off >>= 1)
        contrib += __shfl_down_sync(0xffffffffu, contrib, off);
    if (lane == 0 && contrib != 0.0) atomicAdd(&s_neg, contrib);
    __syncthreads();

    if (tid == 0) {
        double np = (npos > 0) ? (double)npos : 1.0;
        out[0] = (float)((g_pos_loss + s_neg + g_loc_loss) / np);
    }

    // ---- re-zero scratch so the next graph replay starts clean ----
    __syncthreads();
    for (int i = tid; i < NBINS; i += 256) {
        g_hist_cnt[i] = 0;
        g_hist_sum[i] = 0.0f;
    }
    if (tid == 0) {
        g_npos = 0; g_pos_loss = 0.0; g_loc_loss = 0.0; g_done = 0u;
    }
}

// ---------------- entry point ----------------
extern "C" void kernel_launch(void* const* d_in, const int* in_sizes, int n_in,
                              void* d_out, int out_size)
{
    const float* y_pred = (const float*)d_in[0];
    const float* y_true = (const float*)d_in[1];
    float* out = (float*)d_out;

    int nanch = in_sizes[0] / SLOTS;

    ssd_main_kernel<<<NBLOCKS, 256>>>(y_pred, y_true, nanch, out);
}